// round 5
// baseline (speedup 1.0000x reference)
#include <cuda_runtime.h>
#include <math.h>

#define BB 32
#define TT 1024
#define VV 128
#define EE 512
#define HH 1024
#define GG 3072

#define NC 128           // persistent CTAs (1 per SM)
#define RT 512           // threads per recurrence CTA (16 warps, 8 k-partitions)
// SMEM: U4 8192*16=131072 ; U2 8192*8=65536 ; Gsm 12288 ; red 7*3*2*64*8=21504
#define SMEM_RECUR (131072 + 65536 + 12288 + 21504)   // 230400 <= 232448

// ------------------------- device scratch (no mallocs) -----------------------
__device__ float    d_G[(size_t)VV * GG];            // input gates per vocab id
__device__ float    d_hbuf[2 * HH * BB];             // double-buffered h, [buf][k][b]
__device__ float    d_hs[(size_t)TT * BB * HH];      // hidden states [t][b][h]
__device__ int      d_tokT[TT * BB];                 // transposed tokens [t][b]
__device__ unsigned d_arrive[NC];                    // per-CTA arrival flags

// ------------------------------- helpers -------------------------------------
typedef unsigned long long ull;

__device__ __forceinline__ void fma2(ull& acc, ull a, ull b) {
    asm("fma.rn.f32x2 %0, %1, %2, %0;" : "+l"(acc) : "l"(a), "l"(b));
}
__device__ __forceinline__ void add2(ull& acc, ull a) {
    asm("add.rn.f32x2 %0, %1, %0;" : "+l"(acc) : "l"(a));
}
__device__ __forceinline__ float2 unpack2(ull v) {
    float2 f;
    asm("mov.b64 {%0, %1}, %2;" : "=f"(f.x), "=f"(f.y) : "l"(v));
    return f;
}
__device__ __forceinline__ float fsig(float x) {          // sigmoid, ~2ulp
    return __frcp_rn(1.0f + __expf(-x));
}
__device__ __forceinline__ float ftanh_(float x) {        // tanh via exp, ~1e-7
    return 1.0f - 2.0f * __frcp_rn(1.0f + __expf(2.0f * x));
}

// ---------------- k_gin: G[v,g] = emb[v]@Wk + b_in ---------------------------
__global__ void k_gin(const float* __restrict__ emb,
                      const float* __restrict__ Wk,
                      const float* __restrict__ b_in) {
    __shared__ float esm[8][EE];
    const int g  = blockIdx.x * 128 + threadIdx.x;   // 0..3071
    const int v0 = blockIdx.y * 8;

    for (int i = threadIdx.x; i < 8 * EE; i += 128)
        esm[i >> 9][i & (EE - 1)] = emb[(size_t)v0 * EE + i];
    __syncthreads();

    float acc[8];
    const float bi = b_in[g];
#pragma unroll
    for (int i = 0; i < 8; i++) acc[i] = bi;

    for (int e = 0; e < EE; e++) {
        float w = Wk[(size_t)e * GG + g];
#pragma unroll
        for (int i = 0; i < 8; i++) acc[i] = fmaf(esm[i][e], w, acc[i]);
    }
#pragma unroll
    for (int i = 0; i < 8; i++) d_G[(size_t)(v0 + i) * GG + g] = acc[i];
}

// ---------------- k_init: transpose tokens, zero h buf0, reset flags ---------
__global__ void k_init(const int* __restrict__ tokens) {
    int b = blockIdx.x, t = threadIdx.x;
    d_tokT[t * BB + b] = tokens[b * TT + t];
    d_hbuf[b * TT + t] = 0.0f;       // covers exactly HH*BB = 32768 floats (buf 0)
    if (b == 0 && t < NC) d_arrive[t] = 0u;
}

// ---------------- k_recur: persistent GRU scan -------------------------------
// 512 threads = 8 k-partitions x 64 threads.  Thread (col, bq) handles hidden
// column j = cta*8+col for 4 batches b0..b0+3, k-range [p*128, p*128+128).
__global__ void __launch_bounds__(RT, 1)
k_recur(const float* __restrict__ Uk, const float* __restrict__ b_rec) {
    extern __shared__ char sm_[];
    float4* U4  = (float4*)sm_;                          // [k*8+col] {uz,uz,ur,ur}
    float2* U2  = (float2*)(sm_ + 131072);               // [k*8+col] {uh,uh}
    float*  Gsm = (float*)(sm_ + 131072 + 65536);        // [v*24 + col*3 + gate]
    ull*    red = (ull*)(sm_ + 131072 + 65536 + 12288);  // [7][3][64][2] ull

    const int tid  = threadIdx.x;
    const int cta  = blockIdx.x;
    const int p    = tid >> 6;         // k-partition 0..7
    const int l    = tid & 63;
    const int col  = l & 7;
    const int bq   = l >> 3;           // 0..7
    const int b0   = bq * 4;
    const int j    = cta * 8 + col;    // global hidden column
    const int k0p  = p * 128;

    // one-time SMEM fills
    for (int idx = tid; idx < 8192; idx += RT) {
        int k = idx >> 3, cc = idx & 7, jj = cta * 8 + cc;
        float uz = Uk[(size_t)k * GG + jj];
        float ur = Uk[(size_t)k * GG + HH + jj];
        float uh = Uk[(size_t)k * GG + 2 * HH + jj];
        U4[idx] = make_float4(uz, uz, ur, ur);
        U2[idx] = make_float2(uh, uh);
    }
    for (int idx = tid; idx < VV * 8; idx += RT) {
        int v = idx >> 3, cc = idx & 7, jj = cta * 8 + cc;
        Gsm[v * 24 + cc * 3 + 0] = d_G[(size_t)v * GG + jj];
        Gsm[v * 24 + cc * 3 + 1] = d_G[(size_t)v * GG + HH + jj];
        Gsm[v * 24 + cc * 3 + 2] = d_G[(size_t)v * GG + 2 * HH + jj];
    }
    const float brz = b_rec[j];
    const float brr = b_rec[HH + j];
    const float brh = b_rec[2 * HH + j];
    __syncthreads();

    float hr0 = 0.f, hr1 = 0.f, hr2 = 0.f, hr3 = 0.f;   // own h (partition 0)

    for (int t = 0; t < TT; ++t) {
        const int rb = t & 1, wb = rb ^ 1;
        const float* hsrc = d_hbuf + rb * (HH * BB);

        // prefetch this step's tokens (consumed only in the tail)
        int4 tk4;
        if (p == 0) tk4 = __ldcg((const int4*)&d_tokT[t * BB + b0]);

        ull az0 = 0ull, az1 = 0ull, ar0 = 0ull, ar1 = 0ull, ah0 = 0ull, ah1 = 0ull;

#pragma unroll 4
        for (int kk = 0; kk < 128; ++kk) {
            int k = k0p + kk;
            ulonglong2 h2 = __ldcg((const ulonglong2*)(hsrc + k * BB + b0));
            ulonglong2 uzr = *reinterpret_cast<const ulonglong2*>(&U4[(k << 3) + col]);
            ull uh = *reinterpret_cast<const ull*>(&U2[(k << 3) + col]);
            fma2(az0, h2.x, uzr.x);
            fma2(az1, h2.y, uzr.x);
            fma2(ar0, h2.x, uzr.y);
            fma2(ar1, h2.y, uzr.y);
            fma2(ah0, h2.x, uh);
            fma2(ah1, h2.y, uh);
        }

        if (p != 0) {
            ull* rp = red + (size_t)(p - 1) * 384;       // [3][64][2]
            *((ulonglong2*)(rp + 0 * 128) + l) = make_ulonglong2(az0, az1);
            *((ulonglong2*)(rp + 1 * 128) + l) = make_ulonglong2(ar0, ar1);
            *((ulonglong2*)(rp + 2 * 128) + l) = make_ulonglong2(ah0, ah1);
        }
        __syncthreads();

        if (p == 0) {
#pragma unroll
            for (int q = 0; q < 7; ++q) {
                const ull* rp = red + (size_t)q * 384;
                ulonglong2 vz = *((const ulonglong2*)(rp + 0 * 128) + l);
                ulonglong2 vr = *((const ulonglong2*)(rp + 1 * 128) + l);
                ulonglong2 vh = *((const ulonglong2*)(rp + 2 * 128) + l);
                add2(az0, vz.x); add2(az1, vz.y);
                add2(ar0, vr.x); add2(ar1, vr.y);
                add2(ah0, vh.x); add2(ah1, vh.y);
            }
            float2 fz0 = unpack2(az0), fz1 = unpack2(az1);
            float2 fr0 = unpack2(ar0), fr1 = unpack2(ar1);
            float2 fh0 = unpack2(ah0), fh1 = unpack2(ah1);

            const float* g0 = &Gsm[tk4.x * 24 + col * 3];
            const float* g1 = &Gsm[tk4.y * 24 + col * 3];
            const float* g2 = &Gsm[tk4.z * 24 + col * 3];
            const float* g3 = &Gsm[tk4.w * 24 + col * 3];

            // Keras gate order (z, r, h), reset_after=True
            float z, r, hc;
            z   = fsig(g0[0] + fz0.x + brz);
            r   = fsig(g0[1] + fr0.x + brr);
            hc  = ftanh_(g0[2] + r * (fh0.x + brh));
            hr0 = z * hr0 + (1.0f - z) * hc;

            z   = fsig(g1[0] + fz0.y + brz);
            r   = fsig(g1[1] + fr0.y + brr);
            hc  = ftanh_(g1[2] + r * (fh0.y + brh));
            hr1 = z * hr1 + (1.0f - z) * hc;

            z   = fsig(g2[0] + fz1.x + brz);
            r   = fsig(g2[1] + fr1.x + brr);
            hc  = ftanh_(g2[2] + r * (fh1.x + brh));
            hr2 = z * hr2 + (1.0f - z) * hc;

            z   = fsig(g3[0] + fz1.y + brz);
            r   = fsig(g3[1] + fr1.y + brr);
            hc  = ftanh_(g3[2] + r * (fh1.y + brh));
            hr3 = z * hr3 + (1.0f - z) * hc;

            __stcg((float4*)(d_hbuf + wb * (HH * BB) + j * BB + b0),
                   make_float4(hr0, hr1, hr2, hr3));
            d_hs[((size_t)t * BB + b0 + 0) * HH + j] = hr0;
            d_hs[((size_t)t * BB + b0 + 1) * HH + j] = hr1;
            d_hs[((size_t)t * BB + b0 + 2) * HH + j] = hr2;
            d_hs[((size_t)t * BB + b0 + 3) * HH + j] = hr3;
        }

        // -------- grid barrier: per-CTA flag array, monotonic values --------
        __threadfence();                    // release h stores (all threads)
        __syncthreads();
        if (tid == 0) ((volatile unsigned*)d_arrive)[cta] = (unsigned)(t + 1);
        if (tid < NC) {
            while (((volatile unsigned*)d_arrive)[tid] < (unsigned)(t + 1)) { }
        }
        __syncthreads();
        __threadfence();                    // acquire before next step's loads
    }
}

// ---------------- k_logits: out[b,t,:] = hs[t,b,:]@Wd + bd -------------------
__global__ void __launch_bounds__(256)
k_logits(const float* __restrict__ Wd, const float* __restrict__ bd,
         float* __restrict__ out) {
    __shared__ float Asm[32 * 68];    // [m][k], padded rows
    __shared__ float Bsm[64 * 128];   // [k][v]

    const int t   = blockIdx.x;
    const int tid = threadIdx.x;
    const int m0  = (tid >> 4) * 2;   // 2 rows per thread
    const int n0  = (tid & 15) * 8;   // 8 cols per thread

    float acc[2][8];
#pragma unroll
    for (int a = 0; a < 2; a++)
#pragma unroll
        for (int q = 0; q < 8; q++) acc[a][q] = 0.0f;

    for (int k0 = 0; k0 < HH; k0 += 64) {
        __syncthreads();
#pragma unroll
        for (int i = 0; i < 2; i++) {
            int fidx = i * 256 + tid;            // 512 float4s of A
            int m = fidx >> 4, k4 = fidx & 15;
            float4 vA = *reinterpret_cast<const float4*>(
                &d_hs[((size_t)t * BB + m) * HH + k0 + k4 * 4]);
            *reinterpret_cast<float4*>(&Asm[m * 68 + k4 * 4]) = vA;
        }
#pragma unroll
        for (int i = 0; i < 8; i++) {
            int fidx = i * 256 + tid;            // 2048 float4s of B
            int kk = fidx >> 5, v4 = fidx & 31;
            float4 vB = *reinterpret_cast<const float4*>(
                &Wd[(size_t)(k0 + kk) * VV + v4 * 4]);
            *reinterpret_cast<float4*>(&Bsm[kk * 128 + v4 * 4]) = vB;
        }
        __syncthreads();

#pragma unroll 4
        for (int kk = 0; kk < 64; ++kk) {
            float a0 = Asm[m0 * 68 + kk];
            float a1 = Asm[(m0 + 1) * 68 + kk];
            float4 q0 = *reinterpret_cast<const float4*>(&Bsm[kk * 128 + n0]);
            float4 q1 = *reinterpret_cast<const float4*>(&Bsm[kk * 128 + n0 + 4]);
            acc[0][0] = fmaf(a0, q0.x, acc[0][0]);
            acc[0][1] = fmaf(a0, q0.y, acc[0][1]);
            acc[0][2] = fmaf(a0, q0.z, acc[0][2]);
            acc[0][3] = fmaf(a0, q0.w, acc[0][3]);
            acc[0][4] = fmaf(a0, q1.x, acc[0][4]);
            acc[0][5] = fmaf(a0, q1.y, acc[0][5]);
            acc[0][6] = fmaf(a0, q1.z, acc[0][6]);
            acc[0][7] = fmaf(a0, q1.w, acc[0][7]);
            acc[1][0] = fmaf(a1, q0.x, acc[1][0]);
            acc[1][1] = fmaf(a1, q0.y, acc[1][1]);
            acc[1][2] = fmaf(a1, q0.z, acc[1][2]);
            acc[1][3] = fmaf(a1, q0.w, acc[1][3]);
            acc[1][4] = fmaf(a1, q1.x, acc[1][4]);
            acc[1][5] = fmaf(a1, q1.y, acc[1][5]);
            acc[1][6] = fmaf(a1, q1.z, acc[1][6]);
            acc[1][7] = fmaf(a1, q1.w, acc[1][7]);
        }
    }

#pragma unroll
    for (int a = 0; a < 2; a++) {
        int m = m0 + a;
        float* op = &out[((size_t)m * TT + t) * VV + n0];
#pragma unroll
        for (int q = 0; q < 8; q++) op[q] = acc[a][q] + bd[n0 + q];
    }
}

// ------------------------------- launch --------------------------------------
extern "C" void kernel_launch(void* const* d_in, const int* in_sizes, int n_in,
                              void* d_out, int out_size) {
    (void)in_sizes; (void)n_in; (void)out_size;
    const int*   tokens = (const int*)  d_in[0];
    const float* emb    = (const float*)d_in[1];
    const float* Wk     = (const float*)d_in[2];
    const float* Uk     = (const float*)d_in[3];
    const float* b_in   = (const float*)d_in[4];
    const float* b_rec  = (const float*)d_in[5];
    const float* Wd     = (const float*)d_in[6];
    const float* bd     = (const float*)d_in[7];
    float* out = (float*)d_out;

    cudaFuncSetAttribute(k_recur, cudaFuncAttributeMaxDynamicSharedMemorySize, SMEM_RECUR);

    dim3 gin_grid(GG / 128, VV / 8);
    k_gin<<<gin_grid, 128>>>(emb, Wk, b_in);
    k_init<<<BB, TT>>>(tokens);
    k_recur<<<NC, RT, SMEM_RECUR>>>(Uk, b_rec);
    k_logits<<<TT, 256>>>(Wd, bd, out);
}

// round 7
// speedup vs baseline: 2.5253x; 2.5253x over previous
#include <cuda_runtime.h>
#include <math.h>

#define BB 32
#define TT 1024
#define VV 128
#define EE 512
#define HH 1024
#define GG 3072

#define NC 128           // persistent CTAs (1 per SM)
#define RT 512           // 16 warps; warp w owns k-range [w*64, w*64+64)

// SMEM layout for k_recur
#define SM_B 0           // Bsm: tf32 B-fragments, 16w*8kt*3nt*64 u32 = 98304 B
#define SM_G 98304       // Gsm: 128*24 f32 = 12288 B
#define SM_R 110592      // red: 16 warps * 792 f32 = 50688 B
#define SMEM_RECUR 161280

// ------------------------- device scratch (no mallocs) -----------------------
__device__ float    d_G[(size_t)VV * GG];            // input gates per vocab id
__device__ float    d_hbuf[2 * HH * BB];             // double-buffered h, [buf][k][b]
__device__ float    d_hs[(size_t)TT * BB * HH];      // hidden states [t][b][h]
__device__ int      d_tokT[TT * BB];                 // transposed tokens [t][b]
__device__ unsigned d_bar;                           // grid barrier counter

// ------------------------------- helpers -------------------------------------
__device__ __forceinline__ float fsig(float x) { return __frcp_rn(1.0f + __expf(-x)); }
__device__ __forceinline__ float ftanh_(float x) {
    return 1.0f - 2.0f * __frcp_rn(1.0f + __expf(2.0f * x));
}
__device__ __forceinline__ unsigned cvt_tf32(unsigned x) {   // in-place fp32->tf32
    asm("cvt.rna.tf32.f32 %0, %0;" : "+r"(x));
    return x;
}
__device__ __forceinline__ void mma_tf32(float* d, const unsigned* a,
                                         unsigned b0, unsigned b1) {
    asm("mma.sync.aligned.m16n8k8.row.col.f32.tf32.tf32.f32 "
        "{%0,%1,%2,%3}, {%4,%5,%6,%7}, {%8,%9}, {%0,%1,%2,%3};"
        : "+f"(d[0]), "+f"(d[1]), "+f"(d[2]), "+f"(d[3])
        : "r"(a[0]), "r"(a[1]), "r"(a[2]), "r"(a[3]), "r"(b0), "r"(b1));
}

// ---------------- k_gin: G[v,g] = emb[v]@Wk + b_in ; reset barrier -----------
__global__ void k_gin(const float* __restrict__ emb,
                      const float* __restrict__ Wk,
                      const float* __restrict__ b_in) {
    if (blockIdx.x == 0 && blockIdx.y == 0 && threadIdx.x == 0) d_bar = 0u;

    __shared__ float esm[8][EE];
    const int g  = blockIdx.x * 128 + threadIdx.x;
    const int v0 = blockIdx.y * 8;

    for (int i = threadIdx.x; i < 8 * EE; i += 128)
        esm[i >> 9][i & (EE - 1)] = emb[(size_t)v0 * EE + i];
    __syncthreads();

    float acc[8];
    const float bi = b_in[g];
#pragma unroll
    for (int i = 0; i < 8; i++) acc[i] = bi;

    for (int e = 0; e < EE; e++) {
        float w = Wk[(size_t)e * GG + g];
#pragma unroll
        for (int i = 0; i < 8; i++) acc[i] = fmaf(esm[i][e], w, acc[i]);
    }
#pragma unroll
    for (int i = 0; i < 8; i++) d_G[(size_t)(v0 + i) * GG + g] = acc[i];
}

// ---------------- k_init: transpose tokens, zero h buffer 0 ------------------
__global__ void k_init(const int* __restrict__ tokens) {
    int b = blockIdx.x, t = threadIdx.x;
    d_tokT[t * BB + b] = tokens[b * TT + t];
    d_hbuf[b * TT + t] = 0.0f;       // covers exactly HH*BB = 32768 floats (buf 0)
}

// ---------------- k_recur: persistent GRU scan via tf32 mma.sync -------------
// Per CTA/step: out[b, n] = sum_k h[b][k] * U[k][n],  M=32, N=24 (3 gates x 8
// cols), K=1024.  Warp w handles k in [w*64, (w+1)*64): 8 k-tiles of
// m16n8k8, 2 M-tiles x 3 N-tiles, fp32 accumulate; cross-warp SMEM reduce;
// 256 owner threads apply the GRU nonlinearity (one per (batch, col)).
__global__ void __launch_bounds__(RT, 1)
k_recur(const float* __restrict__ Uk, const float* __restrict__ b_rec) {
    extern __shared__ char sm_[];
    unsigned* Bsm = (unsigned*)(sm_ + SM_B);
    float*    Gsm = (float*)(sm_ + SM_G);     // [v*24 + col*3 + gate]
    float*    red = (float*)(sm_ + SM_R);     // [w][n*33 + b]

    const int tid  = threadIdx.x;
    const int cta  = blockIdx.x;
    const int w    = tid >> 5;
    const int lane = tid & 31;
    const int g    = lane >> 2;     // groupID 0..7
    const int tig  = lane & 3;      // threadID-in-group 0..3

    // owner mapping (tid < 256): one (batch, col) h element per thread
    const int b_o   = tid >> 3;
    const int col_o = tid & 7;
    const int j_o   = cta * 8 + col_o;

    // ---- one-time: B fragments (tf32 U) into SMEM ----
    // B-frag for (k-tile kt, n-tile nt): b0 = U[k = w*64+kt*8+tig][n = nt*8+g],
    // b1 = U[k+4][n].  n-tile nt == gate (z=0, r=1, h=2); n&7 == column.
#pragma unroll 1
    for (int kt = 0; kt < 8; ++kt) {
        for (int nt = 0; nt < 3; ++nt) {
            int k = w * 64 + kt * 8 + tig;
            size_t bcol = (size_t)nt * HH + cta * 8 + g;
            unsigned u0 = __float_as_uint(Uk[(size_t)k * GG + bcol]);
            unsigned u1 = __float_as_uint(Uk[(size_t)(k + 4) * GG + bcol]);
            int o = ((w * 8 + kt) * 3 + nt) * 64 + lane * 2;
            Bsm[o]     = cvt_tf32(u0);
            Bsm[o + 1] = cvt_tf32(u1);
        }
    }
    for (int idx = tid; idx < VV * 8; idx += RT) {
        int v = idx >> 3, cc = idx & 7, jj = cta * 8 + cc;
        Gsm[v * 24 + cc * 3 + 0] = d_G[(size_t)v * GG + jj];
        Gsm[v * 24 + cc * 3 + 1] = d_G[(size_t)v * GG + HH + jj];
        Gsm[v * 24 + cc * 3 + 2] = d_G[(size_t)v * GG + 2 * HH + jj];
    }
    const float brz = b_rec[j_o];
    const float brr = b_rec[HH + j_o];
    const float brh = b_rec[2 * HH + j_o];
    __syncthreads();

    float hown = 0.0f;               // owner's h element

    for (int t = 0; t < TT; ++t) {
        const int rb = t & 1, wb = rb ^ 1;
        const unsigned* hb = (const unsigned*)(d_hbuf + rb * (HH * BB));

        int tk = 0;
        if (tid < 256) tk = __ldcg(&d_tokT[t * BB + b_o]);

        // ---- phase 1: 64 independent A-element loads (fp32 bits) ----
        // A-frag (m16n8k8, A row-major = h[b][k]):
        //   a0=(g,tig) a1=(g+8,tig) a2=(g,tig+4) a3=(g+8,tig+4); m-tile1: rows+16
        unsigned A[64];
        {
            const int krow0 = (w * 64 + tig) * BB;
#pragma unroll
            for (int kt = 0; kt < 8; ++kt) {
                int r0 = krow0 + kt * 8 * BB;     // row k   = w*64+kt*8+tig
                int r1 = r0 + 4 * BB;             // row k+4
                A[kt * 8 + 0] = __ldcg(hb + r0 + g);
                A[kt * 8 + 1] = __ldcg(hb + r0 + g + 8);
                A[kt * 8 + 2] = __ldcg(hb + r1 + g);
                A[kt * 8 + 3] = __ldcg(hb + r1 + g + 8);
                A[kt * 8 + 4] = __ldcg(hb + r0 + g + 16);
                A[kt * 8 + 5] = __ldcg(hb + r0 + g + 24);
                A[kt * 8 + 6] = __ldcg(hb + r1 + g + 16);
                A[kt * 8 + 7] = __ldcg(hb + r1 + g + 24);
            }
        }
        // ---- phase 2: in-place tf32 conversion ----
#pragma unroll
        for (int i = 0; i < 64; ++i) A[i] = cvt_tf32(A[i]);

        // ---- phase 3: 48 MMAs ----
        float D[6][4];
#pragma unroll
        for (int i = 0; i < 6; ++i)
#pragma unroll
            for (int q = 0; q < 4; ++q) D[i][q] = 0.0f;

#pragma unroll
        for (int kt = 0; kt < 8; ++kt) {
#pragma unroll
            for (int nt = 0; nt < 3; ++nt) {
                uint2 bf = *(const uint2*)&Bsm[((w * 8 + kt) * 3 + nt) * 64 + lane * 2];
                mma_tf32(D[nt],     &A[kt * 8],     bf.x, bf.y);   // batches 0-15
                mma_tf32(D[3 + nt], &A[kt * 8 + 4], bf.x, bf.y);   // batches 16-31
            }
        }

        // ---- cross-warp reduction via SMEM ----
        // D-frag: d0=(g, tig*2) d1=(g, tig*2+1) d2=(g+8, tig*2) d3=(g+8, tig*2+1)
        {
            float* rw = red + w * 792;
#pragma unroll
            for (int mt = 0; mt < 2; ++mt)
#pragma unroll
                for (int nt = 0; nt < 3; ++nt) {
                    const float* dd = D[mt * 3 + nt];
                    int b = mt * 16 + g;
                    int n = nt * 8 + tig * 2;
                    rw[n * 33 + b]           = dd[0];
                    rw[(n + 1) * 33 + b]     = dd[1];
                    rw[n * 33 + b + 8]       = dd[2];
                    rw[(n + 1) * 33 + b + 8] = dd[3];
                }
        }
        __syncthreads();

        // ---- owners: reduce 16 warps, apply GRU gates ----
        if (tid < 256) {
            float accz = 0.f, accr = 0.f, acch = 0.f;
#pragma unroll
            for (int ww = 0; ww < 16; ++ww) {
                const float* rr = red + ww * 792;
                accz += rr[col_o * 33 + b_o];
                accr += rr[(8 + col_o) * 33 + b_o];
                acch += rr[(16 + col_o) * 33 + b_o];
            }
            const float* gp = &Gsm[tk * 24 + col_o * 3];
            // Keras gate order (z, r, h), reset_after=True
            float z  = fsig(gp[0] + accz + brz);
            float r  = fsig(gp[1] + accr + brr);
            float hc = ftanh_(gp[2] + r * (acch + brh));
            hown = z * hown + (1.0f - z) * hc;

            __stcg(&d_hbuf[wb * (HH * BB) + j_o * BB + b_o], hown);
            d_hs[((size_t)t * BB + b_o) * HH + j_o] = hown;
        }

        // ---- grid barrier (proven in R3/R4): all-thread fence + atomic ----
        __threadfence();
        __syncthreads();
        if (tid == 0) {
            atomicAdd(&d_bar, 1u);
            while (*((volatile unsigned*)&d_bar) < (unsigned)NC * (unsigned)(t + 1)) { }
            __threadfence();
        }
        __syncthreads();
    }
}

// ---------------- k_logits: out[b,t,:] = hs[t,b,:]@Wd + bd -------------------
__global__ void __launch_bounds__(256)
k_logits(const float* __restrict__ Wd, const float* __restrict__ bd,
         float* __restrict__ out) {
    __shared__ float Asm[32 * 68];
    __shared__ float Bsm2[64 * 128];

    const int t   = blockIdx.x;
    const int tid = threadIdx.x;
    const int m0  = (tid >> 4) * 2;
    const int n0  = (tid & 15) * 8;

    float acc[2][8];
#pragma unroll
    for (int a = 0; a < 2; a++)
#pragma unroll
        for (int q = 0; q < 8; q++) acc[a][q] = 0.0f;

    for (int k0 = 0; k0 < HH; k0 += 64) {
        __syncthreads();
#pragma unroll
        for (int i = 0; i < 2; i++) {
            int fidx = i * 256 + tid;
            int m = fidx >> 4, k4 = fidx & 15;
            float4 vA = *reinterpret_cast<const float4*>(
                &d_hs[((size_t)t * BB + m) * HH + k0 + k4 * 4]);
            *reinterpret_cast<float4*>(&Asm[m * 68 + k4 * 4]) = vA;
        }
#pragma unroll
        for (int i = 0; i < 8; i++) {
            int fidx = i * 256 + tid;
            int kk = fidx >> 5, v4 = fidx & 31;
            float4 vB = *reinterpret_cast<const float4*>(
                &Wd[(size_t)(k0 + kk) * VV + v4 * 4]);
            *reinterpret_cast<float4*>(&Bsm2[kk * 128 + v4 * 4]) = vB;
        }
        __syncthreads();

#pragma unroll 4
        for (int kk = 0; kk < 64; ++kk) {
            float a0 = Asm[m0 * 68 + kk];
            float a1 = Asm[(m0 + 1) * 68 + kk];
            float4 q0 = *reinterpret_cast<const float4*>(&Bsm2[kk * 128 + n0]);
            float4 q1 = *reinterpret_cast<const float4*>(&Bsm2[kk * 128 + n0 + 4]);
            acc[0][0] = fmaf(a0, q0.x, acc[0][0]);
            acc[0][1] = fmaf(a0, q0.y, acc[0][1]);
            acc[0][2] = fmaf(a0, q0.z, acc[0][2]);
            acc[0][3] = fmaf(a0, q0.w, acc[0][3]);
            acc[0][4] = fmaf(a0, q1.x, acc[0][4]);
            acc[0][5] = fmaf(a0, q1.y, acc[0][5]);
            acc[0][6] = fmaf(a0, q1.z, acc[0][6]);
            acc[0][7] = fmaf(a0, q1.w, acc[0][7]);
            acc[1][0] = fmaf(a1, q0.x, acc[1][0]);
            acc[1][1] = fmaf(a1, q0.y, acc[1][1]);
            acc[1][2] = fmaf(a1, q0.z, acc[1][2]);
            acc[1][3] = fmaf(a1, q0.w, acc[1][3]);
            acc[1][4] = fmaf(a1, q1.x, acc[1][4]);
            acc[1][5] = fmaf(a1, q1.y, acc[1][5]);
            acc[1][6] = fmaf(a1, q1.z, acc[1][6]);
            acc[1][7] = fmaf(a1, q1.w, acc[1][7]);
        }
    }

#pragma unroll
    for (int a = 0; a < 2; a++) {
        int m = m0 + a;
        float* op = &out[((size_t)m * TT + t) * VV + n0];
#pragma unroll
        for (int q = 0; q < 8; q++) op[q] = acc[a][q] + bd[n0 + q];
    }
}

// ------------------------------- launch --------------------------------------
extern "C" void kernel_launch(void* const* d_in, const int* in_sizes, int n_in,
                              void* d_out, int out_size) {
    (void)in_sizes; (void)n_in; (void)out_size;
    const int*   tokens = (const int*)  d_in[0];
    const float* emb    = (const float*)d_in[1];
    const float* Wk     = (const float*)d_in[2];
    const float* Uk     = (const float*)d_in[3];
    const float* b_in   = (const float*)d_in[4];
    const float* b_rec  = (const float*)d_in[5];
    const float* Wd     = (const float*)d_in[6];
    const float* bd     = (const float*)d_in[7];
    float* out = (float*)d_out;

    cudaFuncSetAttribute(k_recur, cudaFuncAttributeMaxDynamicSharedMemorySize, SMEM_RECUR);

    dim3 gin_grid(GG / 128, VV / 8);
    k_gin<<<gin_grid, 128>>>(emb, Wk, b_in);
    k_init<<<BB, TT>>>(tokens);
    k_recur<<<NC, RT, SMEM_RECUR>>>(Uk, b_rec);
    k_logits<<<TT, 256>>>(Wd, bd, out);
}

// round 8
// speedup vs baseline: 3.2329x; 1.2802x over previous
#include <cuda_runtime.h>
#include <math.h>

#define BB 32
#define TT 1024
#define VV 128
#define EE 512
#define HH 1024
#define GG 3072

#define NC 128           // persistent CTAs (1 per SM)
#define RT 512           // 16 warps; warp w owns k-range [w*64, w*64+64)

// SMEM layout for k_recur
#define SM_B 0           // Bsm: tf32 B-fragments, 16w*8kt*3nt*64 u32 = 98304 B
#define SM_G 98304       // Gsm: 128*24 f32 = 12288 B
#define SM_R 110592      // red: 16 warps * 792 f32 = 50688 B
#define SMEM_RECUR 161280

// ------------------------- device scratch (no mallocs) -----------------------
__device__ float    d_G[(size_t)VV * GG];            // input gates per vocab id
__device__ __align__(128) float d_hbuf[2 * HH * BB]; // double-buffered h, [buf][k][b]
__device__ float    d_hs[(size_t)TT * BB * HH];      // hidden states [t][b][h]
__device__ int      d_tokT[TT * BB];                 // transposed tokens [t][b]
__device__ unsigned d_bar;                           // grid barrier counter

// ------------------------------- helpers -------------------------------------
__device__ __forceinline__ float fsig(float x) { return __frcp_rn(1.0f + __expf(-x)); }
__device__ __forceinline__ float ftanh_(float x) {
    return 1.0f - 2.0f * __frcp_rn(1.0f + __expf(2.0f * x));
}
__device__ __forceinline__ unsigned cvt_tf32(unsigned x) {   // in-place fp32->tf32
    asm("cvt.rna.tf32.f32 %0, %0;" : "+r"(x));
    return x;
}
__device__ __forceinline__ void mma_tf32(float* d, unsigned a0, unsigned a1,
                                         unsigned a2, unsigned a3,
                                         unsigned b0, unsigned b1) {
    asm("mma.sync.aligned.m16n8k8.row.col.f32.tf32.tf32.f32 "
        "{%0,%1,%2,%3}, {%4,%5,%6,%7}, {%8,%9}, {%0,%1,%2,%3};"
        : "+f"(d[0]), "+f"(d[1]), "+f"(d[2]), "+f"(d[3])
        : "r"(a0), "r"(a1), "r"(a2), "r"(a3), "r"(b0), "r"(b1));
}

// ---------------- k_gin: G[v,g] = emb[v]@Wk + b_in ; reset barrier -----------
__global__ void k_gin(const float* __restrict__ emb,
                      const float* __restrict__ Wk,
                      const float* __restrict__ b_in) {
    if (blockIdx.x == 0 && blockIdx.y == 0 && threadIdx.x == 0) d_bar = 0u;

    __shared__ float esm[8][EE];
    const int g  = blockIdx.x * 128 + threadIdx.x;
    const int v0 = blockIdx.y * 8;

    for (int i = threadIdx.x; i < 8 * EE; i += 128)
        esm[i >> 9][i & (EE - 1)] = emb[(size_t)v0 * EE + i];
    __syncthreads();

    float acc[8];
    const float bi = b_in[g];
#pragma unroll
    for (int i = 0; i < 8; i++) acc[i] = bi;

    for (int e = 0; e < EE; e++) {
        float w = Wk[(size_t)e * GG + g];
#pragma unroll
        for (int i = 0; i < 8; i++) acc[i] = fmaf(esm[i][e], w, acc[i]);
    }
#pragma unroll
    for (int i = 0; i < 8; i++) d_G[(size_t)(v0 + i) * GG + g] = acc[i];
}

// ---------------- k_init: transpose tokens, zero h buffer 0 ------------------
__global__ void k_init(const int* __restrict__ tokens) {
    int b = blockIdx.x, t = threadIdx.x;
    d_tokT[t * BB + b] = tokens[b * TT + t];
    d_hbuf[b * TT + t] = 0.0f;       // covers exactly HH*BB = 32768 floats (buf 0)
}

// ---------------- k_recur: persistent GRU scan via tf32 mma.sync -------------
// Per CTA/step: out[b, n] = sum_k h[b][k] * U[k][n],  M=32, N=24, K=1024.
// Warp w: k in [w*64, (w+1)*64), 8 k-tiles m16n8k8, 2 M-tiles x 3 N-tiles.
// BATCH PERMUTATION: MMA tile0 row g -> b=4g, row g+8 -> b=4g+1;
//                    tile1 row g -> b=4g+2, row g+8 -> b=4g+3.
// => each thread's 4 same-k A-regs are h[k][4g..4g+3]: ONE LDG.128.
// Owners un-permute with mr = ((b&2)>>1)*16 + (b>>2) + ((b&1)<<3).
__global__ void __launch_bounds__(RT, 1)
k_recur(const float* __restrict__ Uk, const float* __restrict__ b_rec) {
    extern __shared__ char sm_[];
    unsigned* Bsm = (unsigned*)(sm_ + SM_B);
    float*    Gsm = (float*)(sm_ + SM_G);     // [v*24 + col*3 + gate]
    float*    red = (float*)(sm_ + SM_R);     // [w][n*33 + m]

    const int tid  = threadIdx.x;
    const int cta  = blockIdx.x;
    const int w    = tid >> 5;
    const int lane = tid & 31;
    const int g    = lane >> 2;     // groupID 0..7
    const int tig  = lane & 3;      // threadID-in-group 0..3

    // owner mapping (tid < 256): one (batch, col) h element per thread
    const int b_o   = tid >> 3;
    const int col_o = tid & 7;
    const int j_o   = cta * 8 + col_o;
    const int mr    = ((b_o & 2) >> 1) * 16 + (b_o >> 2) + ((b_o & 1) << 3);

    // ---- one-time: B fragments (tf32 U) into SMEM ----
    // B-frag (kt, nt): b0 = U[k=w*64+kt*8+tig][n=nt*8+g], b1 = U[k+4][n].
#pragma unroll 1
    for (int kt = 0; kt < 8; ++kt) {
        for (int nt = 0; nt < 3; ++nt) {
            int k = w * 64 + kt * 8 + tig;
            size_t bcol = (size_t)nt * HH + cta * 8 + g;
            unsigned u0 = __float_as_uint(Uk[(size_t)k * GG + bcol]);
            unsigned u1 = __float_as_uint(Uk[(size_t)(k + 4) * GG + bcol]);
            int o = ((w * 8 + kt) * 3 + nt) * 64 + lane * 2;
            Bsm[o]     = cvt_tf32(u0);
            Bsm[o + 1] = cvt_tf32(u1);
        }
    }
    for (int idx = tid; idx < VV * 8; idx += RT) {
        int v = idx >> 3, cc = idx & 7, jj = cta * 8 + cc;
        Gsm[v * 24 + cc * 3 + 0] = d_G[(size_t)v * GG + jj];
        Gsm[v * 24 + cc * 3 + 1] = d_G[(size_t)v * GG + HH + jj];
        Gsm[v * 24 + cc * 3 + 2] = d_G[(size_t)v * GG + 2 * HH + jj];
    }
    const float brz = b_rec[j_o];
    const float brr = b_rec[HH + j_o];
    const float brh = b_rec[2 * HH + j_o];
    __syncthreads();

    float hown = 0.0f;               // owner's h element

    for (int t = 0; t < TT; ++t) {
        const int rb = t & 1, wb = rb ^ 1;
        const uint4* hb4 = (const uint4*)(d_hbuf + rb * (HH * BB));

        int tk = 0;
        if (tid < 256) tk = __ldcg(&d_tokT[t * BB + b_o]);

        // ---- phase 1: 16 coalesced LDG.128 per thread ----
        // uint4 index of h[k][4g] = k*8 + g ; k = w*64 + kt*8 + tig (and k+4)
        uint4 A0[8], A1[8];
        {
            const int base = (w * 64 + tig) * 8 + g;
#pragma unroll
            for (int kt = 0; kt < 8; ++kt) {
                A0[kt] = __ldcg(hb4 + base + kt * 64);        // k
                A1[kt] = __ldcg(hb4 + base + kt * 64 + 32);   // k+4
            }
        }
        // ---- phase 2: in-place tf32 conversion ----
#pragma unroll
        for (int kt = 0; kt < 8; ++kt) {
            A0[kt].x = cvt_tf32(A0[kt].x); A0[kt].y = cvt_tf32(A0[kt].y);
            A0[kt].z = cvt_tf32(A0[kt].z); A0[kt].w = cvt_tf32(A0[kt].w);
            A1[kt].x = cvt_tf32(A1[kt].x); A1[kt].y = cvt_tf32(A1[kt].y);
            A1[kt].z = cvt_tf32(A1[kt].z); A1[kt].w = cvt_tf32(A1[kt].w);
        }

        // ---- phase 3: 48 MMAs ----
        float D[6][4];
#pragma unroll
        for (int i = 0; i < 6; ++i)
#pragma unroll
            for (int q = 0; q < 4; ++q) D[i][q] = 0.0f;

#pragma unroll
        for (int kt = 0; kt < 8; ++kt) {
#pragma unroll
            for (int nt = 0; nt < 3; ++nt) {
                uint2 bf = *(const uint2*)&Bsm[((w * 8 + kt) * 3 + nt) * 64 + lane * 2];
                // tile0: rows -> b = 4g, 4g+1
                mma_tf32(D[nt],     A0[kt].x, A0[kt].y, A1[kt].x, A1[kt].y, bf.x, bf.y);
                // tile1: rows -> b = 4g+2, 4g+3
                mma_tf32(D[3 + nt], A0[kt].z, A0[kt].w, A1[kt].z, A1[kt].w, bf.x, bf.y);
            }
        }

        // ---- cross-warp reduction via SMEM ----
        // D-frag: d0=(g, tig*2) d1=(g, tig*2+1) d2=(g+8, tig*2) d3=(g+8, tig*2+1)
        {
            float* rw = red + w * 792;
#pragma unroll
            for (int mt = 0; mt < 2; ++mt)
#pragma unroll
                for (int nt = 0; nt < 3; ++nt) {
                    const float* dd = D[mt * 3 + nt];
                    int m = mt * 16 + g;
                    int n = nt * 8 + tig * 2;
                    rw[n * 33 + m]           = dd[0];
                    rw[(n + 1) * 33 + m]     = dd[1];
                    rw[n * 33 + m + 8]       = dd[2];
                    rw[(n + 1) * 33 + m + 8] = dd[3];
                }
        }
        __syncthreads();

        // ---- owners: reduce 16 warps (permuted row mr), apply GRU gates ----
        if (tid < 256) {
            float accz = 0.f, accr = 0.f, acch = 0.f;
#pragma unroll
            for (int ww = 0; ww < 16; ++ww) {
                const float* rr = red + ww * 792;
                accz += rr[col_o * 33 + mr];
                accr += rr[(8 + col_o) * 33 + mr];
                acch += rr[(16 + col_o) * 33 + mr];
            }
            const float* gp = &Gsm[tk * 24 + col_o * 3];
            // Keras gate order (z, r, h), reset_after=True
            float z  = fsig(gp[0] + accz + brz);
            float r  = fsig(gp[1] + accr + brr);
            float hc = ftanh_(gp[2] + r * (acch + brh));
            hown = z * hown + (1.0f - z) * hc;

            __stcg(&d_hbuf[wb * (HH * BB) + j_o * BB + b_o], hown);
        }

        // ---- grid barrier (proven): all-thread fence + atomic ----
        __threadfence();
        __syncthreads();
        if (tid == 0) atomicAdd(&d_bar, 1u);

        // d_hs store off the critical path (read only after kernel ends)
        if (tid < 256)
            d_hs[((size_t)t * BB + b_o) * HH + j_o] = hown;

        if (tid == 0) {
            while (*((volatile unsigned*)&d_bar) < (unsigned)NC * (unsigned)(t + 1)) { }
            __threadfence();
        }
        __syncthreads();
    }
}

// ---------------- k_logits: out[b,t,:] = hs[t,b,:]@Wd + bd -------------------
__global__ void __launch_bounds__(256)
k_logits(const float* __restrict__ Wd, const float* __restrict__ bd,
         float* __restrict__ out) {
    __shared__ float Asm[32 * 68];
    __shared__ float Bsm2[64 * 128];

    const int t   = blockIdx.x;
    const int tid = threadIdx.x;
    const int m0  = (tid >> 4) * 2;
    const int n0  = (tid & 15) * 8;

    float acc[2][8];
#pragma unroll
    for (int a = 0; a < 2; a++)
#pragma unroll
        for (int q = 0; q < 8; q++) acc[a][q] = 0.0f;

    for (int k0 = 0; k0 < HH; k0 += 64) {
        __syncthreads();
#pragma unroll
        for (int i = 0; i < 2; i++) {
            int fidx = i * 256 + tid;
            int m = fidx >> 4, k4 = fidx & 15;
            float4 vA = *reinterpret_cast<const float4*>(
                &d_hs[((size_t)t * BB + m) * HH + k0 + k4 * 4]);
            *reinterpret_cast<float4*>(&Asm[m * 68 + k4 * 4]) = vA;
        }
#pragma unroll
        for (int i = 0; i < 8; i++) {
            int fidx = i * 256 + tid;
            int kk = fidx >> 5, v4 = fidx & 31;
            float4 vB = *reinterpret_cast<const float4*>(
                &Wd[(size_t)(k0 + kk) * VV + v4 * 4]);
            *reinterpret_cast<float4*>(&Bsm2[kk * 128 + v4 * 4]) = vB;
        }
        __syncthreads();

#pragma unroll 4
        for (int kk = 0; kk < 64; ++kk) {
            float a0 = Asm[m0 * 68 + kk];
            float a1 = Asm[(m0 + 1) * 68 + kk];
            float4 q0 = *reinterpret_cast<const float4*>(&Bsm2[kk * 128 + n0]);
            float4 q1 = *reinterpret_cast<const float4*>(&Bsm2[kk * 128 + n0 + 4]);
            acc[0][0] = fmaf(a0, q0.x, acc[0][0]);
            acc[0][1] = fmaf(a0, q0.y, acc[0][1]);
            acc[0][2] = fmaf(a0, q0.z, acc[0][2]);
            acc[0][3] = fmaf(a0, q0.w, acc[0][3]);
            acc[0][4] = fmaf(a0, q1.x, acc[0][4]);
            acc[0][5] = fmaf(a0, q1.y, acc[0][5]);
            acc[0][6] = fmaf(a0, q1.z, acc[0][6]);
            acc[0][7] = fmaf(a0, q1.w, acc[0][7]);
            acc[1][0] = fmaf(a1, q0.x, acc[1][0]);
            acc[1][1] = fmaf(a1, q0.y, acc[1][1]);
            acc[1][2] = fmaf(a1, q0.z, acc[1][2]);
            acc[1][3] = fmaf(a1, q0.w, acc[1][3]);
            acc[1][4] = fmaf(a1, q1.x, acc[1][4]);
            acc[1][5] = fmaf(a1, q1.y, acc[1][5]);
            acc[1][6] = fmaf(a1, q1.z, acc[1][6]);
            acc[1][7] = fmaf(a1, q1.w, acc[1][7]);
        }
    }

#pragma unroll
    for (int a = 0; a < 2; a++) {
        int m = m0 + a;
        float* op = &out[((size_t)m * TT + t) * VV + n0];
#pragma unroll
        for (int q = 0; q < 8; q++) op[q] = acc[a][q] + bd[n0 + q];
    }
}

// ------------------------------- launch --------------------------------------
extern "C" void kernel_launch(void* const* d_in, const int* in_sizes, int n_in,
                              void* d_out, int out_size) {
    (void)in_sizes; (void)n_in; (void)out_size;
    const int*   tokens = (const int*)  d_in[0];
    const float* emb    = (const float*)d_in[1];
    const float* Wk     = (const float*)d_in[2];
    const float* Uk     = (const float*)d_in[3];
    const float* b_in   = (const float*)d_in[4];
    const float* b_rec  = (const float*)d_in[5];
    const float* Wd     = (const float*)d_in[6];
    const float* bd     = (const float*)d_in[7];
    float* out = (float*)d_out;

    cudaFuncSetAttribute(k_recur, cudaFuncAttributeMaxDynamicSharedMemorySize, SMEM_RECUR);

    dim3 gin_grid(GG / 128, VV / 8);
    k_gin<<<gin_grid, 128>>>(emb, Wk, b_in);
    k_init<<<BB, TT>>>(tokens);
    k_recur<<<NC, RT, SMEM_RECUR>>>(Uk, b_rec);
    k_logits<<<TT, 256>>>(Wd, bd, out);
}

// round 9
// speedup vs baseline: 3.6019x; 1.1141x over previous
#include <cuda_runtime.h>
#include <cuda_fp16.h>
#include <math.h>

#define BB 32
#define TT 1024
#define VV 128
#define EE 512
#define HH 1024
#define GG 3072

#define NC 128           // persistent CTAs (1 per SM)
#define RT 512           // 16 warps; warp w owns k-range [w*64, w*64+64)

// SMEM layout for k_recur
#define SM_B 0           // Bsm: f16 B-frags, 16w*4kt*3nt*64 u32 = 49152 B
#define SM_G 49152       // Gsm: 128*24 f32 = 12288 B
#define SM_R 61440       // red: 16 warps * 792 f32 = 50688 B
#define SM_H 112128      // hsm: 32 rows * 1032 halves (2064 B, pad 8) = 66048 B
#define SMEM_RECUR 178176
#define HROW 1032        // padded row length in halves (2064 B == 16 mod 128)

// ------------------------- device scratch (no mallocs) -----------------------
__device__ float    d_G[(size_t)VV * GG];              // input gates per vocab id
__device__ __align__(128) __half d_hbuf16[2 * BB * HH];// double-buffered h, [buf][b][k]
__device__ float    d_hs[(size_t)TT * BB * HH];        // hidden states [t][b][h]
__device__ int      d_tokT[TT * BB];                   // transposed tokens [t][b]
__device__ unsigned d_bar;                             // grid barrier counter

// ------------------------------- helpers -------------------------------------
__device__ __forceinline__ float fsig(float x) { return __frcp_rn(1.0f + __expf(-x)); }
__device__ __forceinline__ float ftanh_(float x) {
    return 1.0f - 2.0f * __frcp_rn(1.0f + __expf(2.0f * x));
}
__device__ __forceinline__ void ldsm4(unsigned* a, unsigned p) {
    asm volatile("ldmatrix.sync.aligned.m8n8.x4.shared.b16 {%0,%1,%2,%3}, [%4];"
                 : "=r"(a[0]), "=r"(a[1]), "=r"(a[2]), "=r"(a[3]) : "r"(p));
}
__device__ __forceinline__ void mma_f16(float* d, const unsigned* a,
                                        unsigned b0, unsigned b1) {
    asm("mma.sync.aligned.m16n8k16.row.col.f32.f16.f16.f32 "
        "{%0,%1,%2,%3}, {%4,%5,%6,%7}, {%8,%9}, {%0,%1,%2,%3};"
        : "+f"(d[0]), "+f"(d[1]), "+f"(d[2]), "+f"(d[3])
        : "r"(a[0]), "r"(a[1]), "r"(a[2]), "r"(a[3]), "r"(b0), "r"(b1));
}
__device__ __forceinline__ unsigned packh2(float lo, float hi) {
    __half2 h = __floats2half2_rn(lo, hi);      // lo -> low 16 bits
    return *reinterpret_cast<unsigned*>(&h);
}

// ---------------- k_gin: G[v,g] = emb[v]@Wk + b_in ; reset barrier -----------
__global__ void k_gin(const float* __restrict__ emb,
                      const float* __restrict__ Wk,
                      const float* __restrict__ b_in) {
    if (blockIdx.x == 0 && blockIdx.y == 0 && threadIdx.x == 0) d_bar = 0u;

    __shared__ float esm[8][EE];
    const int g  = blockIdx.x * 128 + threadIdx.x;
    const int v0 = blockIdx.y * 8;

    for (int i = threadIdx.x; i < 8 * EE; i += 128)
        esm[i >> 9][i & (EE - 1)] = emb[(size_t)v0 * EE + i];
    __syncthreads();

    float acc[8];
    const float bi = b_in[g];
#pragma unroll
    for (int i = 0; i < 8; i++) acc[i] = bi;

    for (int e = 0; e < EE; e++) {
        float w = Wk[(size_t)e * GG + g];
#pragma unroll
        for (int i = 0; i < 8; i++) acc[i] = fmaf(esm[i][e], w, acc[i]);
    }
#pragma unroll
    for (int i = 0; i < 8; i++) d_G[(size_t)(v0 + i) * GG + g] = acc[i];
}

// ---------------- k_init: transpose tokens, zero h buffer 0 ------------------
__global__ void k_init(const int* __restrict__ tokens) {
    int b = blockIdx.x, t = threadIdx.x;
    d_tokT[t * BB + b] = tokens[b * TT + t];
    d_hbuf16[b * HH + t] = __float2half(0.0f);   // covers buf 0: 32*1024 halves
}

// ---------------- k_recur: persistent GRU scan via fp16 mma.sync -------------
// Per CTA/step: out[b, n] = sum_k h[b][k] * U[k][n],  M=32, N=24, K=1024.
// h exchanged in fp16 ([buf][b][k]); staged to padded SMEM; A-frags via
// ldmatrix.x4; warp w: k in [w*64,(w+1)*64) = 4 k16-tiles, 2 M-tiles, 3 N-tiles
// (24 MMAs).  fp32 accumulate; cross-warp SMEM reduce; 256 owner threads
// apply the GRU nonlinearity.  fp16 mantissa (10b) == tf32 mantissa.
__global__ void __launch_bounds__(RT, 1)
k_recur(const float* __restrict__ Uk, const float* __restrict__ b_rec) {
    extern __shared__ char sm_[];
    unsigned* Bsm = (unsigned*)(sm_ + SM_B);
    float*    Gsm = (float*)(sm_ + SM_G);     // [v*24 + col*3 + gate]
    float*    red = (float*)(sm_ + SM_R);     // [w][n*33 + m]
    uint4*    hsm4 = (uint4*)(sm_ + SM_H);    // padded h tile, 129 uint4/row

    const unsigned smb = (unsigned)__cvta_generic_to_shared(sm_);
    const int tid  = threadIdx.x;
    const int cta  = blockIdx.x;
    const int w    = tid >> 5;
    const int lane = tid & 31;
    const int g    = lane >> 2;     // groupID 0..7
    const int tig  = lane & 3;      // threadID-in-group 0..3

    // owner mapping (tid < 256): one (batch, col) h element per thread
    const int b_o   = tid >> 3;
    const int col_o = tid & 7;
    const int j_o   = cta * 8 + col_o;

    // ldmatrix lane pointer offset: row = lane%16 (stride 2064B), col-block +16B
    const unsigned lo_  = (unsigned)((lane & 15) * 2064 + (lane >> 4) * 16);
    const unsigned pM0  = smb + SM_H + lo_ + (unsigned)(w * 128);       // rows 0-15
    const unsigned pM1  = pM0 + 16 * 2064;                              // rows 16-31

    // ---- one-time: B fragments (fp16 U pairs) into SMEM ----
    // b0 = {U[kb+2tig][n], U[kb+2tig+1][n]}, b1 = {U[kb+2tig+8][n], U[kb+2tig+9][n]}
#pragma unroll 1
    for (int kt = 0; kt < 4; ++kt) {
        for (int nt = 0; nt < 3; ++nt) {
            int k = w * 64 + kt * 16 + 2 * tig;
            size_t n = (size_t)nt * HH + cta * 8 + g;
            unsigned b0 = packh2(Uk[(size_t)k * GG + n],
                                 Uk[(size_t)(k + 1) * GG + n]);
            unsigned b1 = packh2(Uk[(size_t)(k + 8) * GG + n],
                                 Uk[(size_t)(k + 9) * GG + n]);
            int o = ((w * 4 + kt) * 3 + nt) * 64 + lane * 2;
            Bsm[o]     = b0;
            Bsm[o + 1] = b1;
        }
    }
    for (int idx = tid; idx < VV * 8; idx += RT) {
        int v = idx >> 3, cc = idx & 7, jj = cta * 8 + cc;
        Gsm[v * 24 + cc * 3 + 0] = d_G[(size_t)v * GG + jj];
        Gsm[v * 24 + cc * 3 + 1] = d_G[(size_t)v * GG + HH + jj];
        Gsm[v * 24 + cc * 3 + 2] = d_G[(size_t)v * GG + 2 * HH + jj];
    }
    const float brz = b_rec[j_o];
    const float brr = b_rec[HH + j_o];
    const float brh = b_rec[2 * HH + j_o];
    __syncthreads();

    float hown = 0.0f;               // owner's h element (fp32 across steps)

    for (int t = 0; t < TT; ++t) {
        const int rb = t & 1, wb = rb ^ 1;

        int tk = 0;
        if (tid < 256) tk = __ldcg(&d_tokT[t * BB + b_o]);

        // ---- stage h (64 KB fp16) global -> padded SMEM, fully coalesced ----
        {
            const uint4* src = (const uint4*)(d_hbuf16 + (size_t)rb * (BB * HH));
#pragma unroll
            for (int i = 0; i < 8; ++i) {
                int idx = i * 512 + tid;          // 0..4095
                int row = idx >> 7, c = idx & 127;
                hsm4[row * 129 + c] = __ldcg(src + idx);
            }
        }
        __syncthreads();

        // ---- 24 MMAs per warp (fp16, k16) ----
        float D[6][4];
#pragma unroll
        for (int i = 0; i < 6; ++i)
#pragma unroll
            for (int q = 0; q < 4; ++q) D[i][q] = 0.0f;

#pragma unroll
        for (int kt = 0; kt < 4; ++kt) {
            unsigned a0[4], a1[4];
            ldsm4(a0, pM0 + kt * 32);             // batches 0-15
            ldsm4(a1, pM1 + kt * 32);             // batches 16-31
#pragma unroll
            for (int nt = 0; nt < 3; ++nt) {
                uint2 bf = *(const uint2*)&Bsm[((w * 4 + kt) * 3 + nt) * 64 + lane * 2];
                mma_f16(D[nt],     a0, bf.x, bf.y);
                mma_f16(D[3 + nt], a1, bf.x, bf.y);
            }
        }

        // ---- cross-warp reduction via SMEM ----
        // D-frag: d0=(g, 2tig) d1=(g, 2tig+1) d2=(g+8, 2tig) d3=(g+8, 2tig+1)
        {
            float* rw = red + w * 792;
#pragma unroll
            for (int mt = 0; mt < 2; ++mt)
#pragma unroll
                for (int nt = 0; nt < 3; ++nt) {
                    const float* dd = D[mt * 3 + nt];
                    int m = mt * 16 + g;
                    int n = nt * 8 + tig * 2;
                    rw[n * 33 + m]           = dd[0];
                    rw[(n + 1) * 33 + m]     = dd[1];
                    rw[n * 33 + m + 8]       = dd[2];
                    rw[(n + 1) * 33 + m + 8] = dd[3];
                }
        }
        __syncthreads();

        // ---- owners: reduce 16 warps, apply GRU gates ----
        if (tid < 256) {
            float accz = 0.f, accr = 0.f, acch = 0.f;
#pragma unroll
            for (int ww = 0; ww < 16; ++ww) {
                const float* rr = red + ww * 792;
                accz += rr[col_o * 33 + b_o];
                accr += rr[(8 + col_o) * 33 + b_o];
                acch += rr[(16 + col_o) * 33 + b_o];
            }
            const float* gp = &Gsm[tk * 24 + col_o * 3];
            // Keras gate order (z, r, h), reset_after=True
            float z  = fsig(gp[0] + accz + brz);
            float r  = fsig(gp[1] + accr + brr);
            float hc = ftanh_(gp[2] + r * (acch + brh));
            hown = z * hown + (1.0f - z) * hc;

            unsigned short hv = __half_as_ushort(__float2half_rn(hown));
            asm volatile("st.global.cg.u16 [%0], %1;"
                         :: "l"(d_hbuf16 + (size_t)wb * (BB * HH) + b_o * HH + j_o),
                            "h"(hv) : "memory");
        }

        // ---- grid barrier (proven): all-thread fence + atomic ----
        __threadfence();
        __syncthreads();
        if (tid == 0) atomicAdd(&d_bar, 1u);

        // d_hs store off the critical path (read only after kernel ends)
        if (tid < 256)
            d_hs[((size_t)t * BB + b_o) * HH + j_o] = hown;

        if (tid == 0) {
            while (*((volatile unsigned*)&d_bar) < (unsigned)NC * (unsigned)(t + 1)) { }
            __threadfence();
        }
        __syncthreads();
    }
}

// ---------------- k_logits: out[b,t,:] = hs[t,b,:]@Wd + bd -------------------
__global__ void __launch_bounds__(256)
k_logits(const float* __restrict__ Wd, const float* __restrict__ bd,
         float* __restrict__ out) {
    __shared__ float Asm[32 * 68];
    __shared__ float Bsm2[64 * 128];

    const int t   = blockIdx.x;
    const int tid = threadIdx.x;
    const int m0  = (tid >> 4) * 2;
    const int n0  = (tid & 15) * 8;

    float acc[2][8];
#pragma unroll
    for (int a = 0; a < 2; a++)
#pragma unroll
        for (int q = 0; q < 8; q++) acc[a][q] = 0.0f;

    for (int k0 = 0; k0 < HH; k0 += 64) {
        __syncthreads();
#pragma unroll
        for (int i = 0; i < 2; i++) {
            int fidx = i * 256 + tid;
            int m = fidx >> 4, k4 = fidx & 15;
            float4 vA = *reinterpret_cast<const float4*>(
                &d_hs[((size_t)t * BB + m) * HH + k0 + k4 * 4]);
            *reinterpret_cast<float4*>(&Asm[m * 68 + k4 * 4]) = vA;
        }
#pragma unroll
        for (int i = 0; i < 8; i++) {
            int fidx = i * 256 + tid;
            int kk = fidx >> 5, v4 = fidx & 31;
            float4 vB = *reinterpret_cast<const float4*>(
                &Wd[(size_t)(k0 + kk) * VV + v4 * 4]);
            *reinterpret_cast<float4*>(&Bsm2[kk * 128 + v4 * 4]) = vB;
        }
        __syncthreads();

#pragma unroll 4
        for (int kk = 0; kk < 64; ++kk) {
            float a0 = Asm[m0 * 68 + kk];
            float a1 = Asm[(m0 + 1) * 68 + kk];
            float4 q0 = *reinterpret_cast<const float4*>(&Bsm2[kk * 128 + n0]);
            float4 q1 = *reinterpret_cast<const float4*>(&Bsm2[kk * 128 + n0 + 4]);
            acc[0][0] = fmaf(a0, q0.x, acc[0][0]);
            acc[0][1] = fmaf(a0, q0.y, acc[0][1]);
            acc[0][2] = fmaf(a0, q0.z, acc[0][2]);
            acc[0][3] = fmaf(a0, q0.w, acc[0][3]);
            acc[0][4] = fmaf(a0, q1.x, acc[0][4]);
            acc[0][5] = fmaf(a0, q1.y, acc[0][5]);
            acc[0][6] = fmaf(a0, q1.z, acc[0][6]);
            acc[0][7] = fmaf(a0, q1.w, acc[0][7]);
            acc[1][0] = fmaf(a1, q0.x, acc[1][0]);
            acc[1][1] = fmaf(a1, q0.y, acc[1][1]);
            acc[1][2] = fmaf(a1, q0.z, acc[1][2]);
            acc[1][3] = fmaf(a1, q0.w, acc[1][3]);
            acc[1][4] = fmaf(a1, q1.x, acc[1][4]);
            acc[1][5] = fmaf(a1, q1.y, acc[1][5]);
            acc[1][6] = fmaf(a1, q1.z, acc[1][6]);
            acc[1][7] = fmaf(a1, q1.w, acc[1][7]);
        }
    }

#pragma unroll
    for (int a = 0; a < 2; a++) {
        int m = m0 + a;
        float* op = &out[((size_t)m * TT + t) * VV + n0];
#pragma unroll
        for (int q = 0; q < 8; q++) op[q] = acc[a][q] + bd[n0 + q];
    }
}

// ------------------------------- launch --------------------------------------
extern "C" void kernel_launch(void* const* d_in, const int* in_sizes, int n_in,
                              void* d_out, int out_size) {
    (void)in_sizes; (void)n_in; (void)out_size;
    const int*   tokens = (const int*)  d_in[0];
    const float* emb    = (const float*)d_in[1];
    const float* Wk     = (const float*)d_in[2];
    const float* Uk     = (const float*)d_in[3];
    const float* b_in   = (const float*)d_in[4];
    const float* b_rec  = (const float*)d_in[5];
    const float* Wd     = (const float*)d_in[6];
    const float* bd     = (const float*)d_in[7];
    float* out = (float*)d_out;

    cudaFuncSetAttribute(k_recur, cudaFuncAttributeMaxDynamicSharedMemorySize, SMEM_RECUR);

    dim3 gin_grid(GG / 128, VV / 8);
    k_gin<<<gin_grid, 128>>>(emb, Wk, b_in);
    k_init<<<BB, TT>>>(tokens);
    k_recur<<<NC, RT, SMEM_RECUR>>>(Uk, b_rec);
    k_logits<<<TT, 256>>>(Wd, bd, out);
}